// round 1
// baseline (speedup 1.0000x reference)
#include <cuda_runtime.h>

#define BB 2
#define SS 2048
#define HH 8
#define DD 64
#define MT 64
#define NT 64
#define NTILES (SS / NT)
#define THREADS 256

#define KS_STRIDE 68
#define ES_STRIDE 68

// ---- helpers -------------------------------------------------------------

__device__ __forceinline__ float ex2f(float x) {
    float y;
    asm("ex2.approx.ftz.f32 %0, %1;" : "=f"(y) : "f"(x));
    return y;
}

__device__ __forceinline__ unsigned long long pk2(float lo, float hi) {
    unsigned long long r;
    asm("mov.b64 %0, {%1, %2};" : "=l"(r) : "f"(lo), "f"(hi));
    return r;
}

__device__ __forceinline__ float2 upk2(unsigned long long p) {
    float lo, hi;
    asm("mov.b64 {%0, %1}, %2;" : "=f"(lo), "=f"(hi) : "l"(p));
    return make_float2(lo, hi);
}

// packed dual-FMA: d = a*b + d elementwise on two f32 lanes
__device__ __forceinline__ void fma2(unsigned long long& d,
                                     unsigned long long a,
                                     unsigned long long b) {
    asm("fma.rn.f32x2 %0, %1, %2, %3;" : "=l"(d) : "l"(a), "l"(b), "l"(d));
}

// ---- kernel --------------------------------------------------------------
//
// grid = (S/MT, H, B), block = 256.
// Per block: one 64-query tile of one (b,h). Streams over 64-key tiles.
// Max-free streaming softmax with 4 accumulators keyed by n%4:
//   cfg1 = (sum of all 4) / (lr0+lr1+lr2+lr3)          [always active]
//   cfg2 = (acc[p]+acc[p+2]) / (lr[p]+lr[p+2])         [if m%2 == (m>>10)&1]
//   cfg3 = acc[0] / lr[0]                              [if m%4 == 0]

__global__ void __launch_bounds__(THREADS)
dilated_attn_kernel(const float* __restrict__ gq, const float* __restrict__ gk,
                    const float* __restrict__ gv, float* __restrict__ gout) {
    extern __shared__ float smem[];
    float* Qs = smem;                         // [MT][64]   (scaled by log2e/8)
    float* Ks = Qs + MT * 64;                 // [NT][68]
    float* Es = Ks + NT * KS_STRIDE;          // [MT][68]   exp(scores)
    float* Vs = Es + MT * ES_STRIDE;          // [NT][64]

    const int tid = threadIdx.x;
    const int m0 = blockIdx.x * MT;
    const int h = blockIdx.y;
    const int b = blockIdx.z;

    const size_t row_stride = (size_t)HH * DD;               // 512 floats
    const size_t bh_off = (size_t)b * SS * row_stride + (size_t)h * DD;
    const float* qb = gq + bh_off + (size_t)m0 * row_stride;
    const float* kb = gk + bh_off;
    const float* vb = gv + bh_off;

    const float QSCALE = 0.18033688011112042f;  // log2(e) / sqrt(64)

    // ---- load Q tile (scaled) ----
#pragma unroll
    for (int idx = tid; idx < MT * 16; idx += THREADS) {
        int m = idx >> 4;
        int d4 = (idx & 15) << 2;
        float4 t = *(const float4*)(qb + (size_t)m * row_stride + d4);
        t.x *= QSCALE; t.y *= QSCALE; t.z *= QSCALE; t.w *= QSCALE;
        *(float4*)(Qs + m * 64 + d4) = t;
    }

    // ---- PV-phase thread mapping: 4 threads per query row, 16 dims each ----
    const int row = tid >> 2;
    const int dbase = (tid & 3) << 4;

    unsigned long long acc2[4][8];  // [n%4][dim-pair]  (two f32 per entry)
#pragma unroll
    for (int r = 0; r < 4; ++r)
#pragma unroll
        for (int i = 0; i < 8; ++i) acc2[r][i] = 0ULL;
    float lr[4] = {0.f, 0.f, 0.f, 0.f};

    // ---- QK-phase thread mapping: 16x16 grid of 4x4 register tiles ----
    const int ty = tid >> 4;
    const int tx = tid & 15;

    for (int t = 0; t < NTILES; ++t) {
        __syncthreads();  // prior PV reads of Vs/Es complete

        // ---- load K,V tiles ----
        const float* kt = kb + (size_t)(t * NT) * row_stride;
        const float* vt = vb + (size_t)(t * NT) * row_stride;
#pragma unroll
        for (int idx = tid; idx < NT * 16; idx += THREADS) {
            int n = idx >> 4;
            int d4 = (idx & 15) << 2;
            float4 kk = *(const float4*)(kt + (size_t)n * row_stride + d4);
            *(float4*)(Ks + n * KS_STRIDE + d4) = kk;
            float4 vv = *(const float4*)(vt + (size_t)n * row_stride + d4);
            *(float4*)(Vs + n * 64 + d4) = vv;
        }
        __syncthreads();

        // ---- QK: s = (q . k) * log2e/8, then Es = 2^s ----
        unsigned long long s2[4][4];
#pragma unroll
        for (int i = 0; i < 4; ++i)
#pragma unroll
            for (int j = 0; j < 4; ++j) s2[i][j] = 0ULL;

#pragma unroll
        for (int k0 = 0; k0 < DD; k0 += 4) {
            unsigned long long qp[4][2], kp[4][2];
#pragma unroll
            for (int i = 0; i < 4; ++i) {
                float4 qv = *(const float4*)(Qs + (4 * ty + i) * 64 + k0);
                qp[i][0] = pk2(qv.x, qv.y);
                qp[i][1] = pk2(qv.z, qv.w);
            }
#pragma unroll
            for (int j = 0; j < 4; ++j) {
                float4 kv = *(const float4*)(Ks + (4 * tx + j) * KS_STRIDE + k0);
                kp[j][0] = pk2(kv.x, kv.y);
                kp[j][1] = pk2(kv.z, kv.w);
            }
#pragma unroll
            for (int i = 0; i < 4; ++i)
#pragma unroll
                for (int j = 0; j < 4; ++j) {
                    fma2(s2[i][j], qp[i][0], kp[j][0]);
                    fma2(s2[i][j], qp[i][1], kp[j][1]);
                }
        }
#pragma unroll
        for (int i = 0; i < 4; ++i)
#pragma unroll
            for (int j = 0; j < 4; ++j) {
                float2 f = upk2(s2[i][j]);
                Es[(4 * ty + i) * ES_STRIDE + (4 * tx + j)] = ex2f(f.x + f.y);
            }
        __syncthreads();

        // ---- PV: route each key into accumulator n%4 ----
        const float* erow = Es + row * ES_STRIDE;
#pragma unroll
        for (int n = 0; n < NT; n += 4) {
            float4 ev = *(const float4*)(erow + n);
            float ej[4] = {ev.x, ev.y, ev.z, ev.w};
#pragma unroll
            for (int j = 0; j < 4; ++j) {
                float e = ej[j];
                lr[j] += e;
                unsigned long long ee = pk2(e, e);
                const float4* vp = (const float4*)(Vs + (n + j) * 64 + dbase);
                float4 v0 = vp[0], v1 = vp[1], v2 = vp[2], v3 = vp[3];
                fma2(acc2[j][0], ee, pk2(v0.x, v0.y));
                fma2(acc2[j][1], ee, pk2(v0.z, v0.w));
                fma2(acc2[j][2], ee, pk2(v1.x, v1.y));
                fma2(acc2[j][3], ee, pk2(v1.z, v1.w));
                fma2(acc2[j][4], ee, pk2(v2.x, v2.y));
                fma2(acc2[j][5], ee, pk2(v2.z, v2.w));
                fma2(acc2[j][6], ee, pk2(v3.x, v3.y));
                fma2(acc2[j][7], ee, pk2(v3.z, v3.w));
            }
        }
    }

    // ---- finalize: combine residue-class accumulators per config ----
    float a0[16], a1[16], a2f[16], a3[16];
#pragma unroll
    for (int i = 0; i < 8; ++i) {
        float2 f;
        f = upk2(acc2[0][i]); a0[2 * i] = f.x; a0[2 * i + 1] = f.y;
        f = upk2(acc2[1][i]); a1[2 * i] = f.x; a1[2 * i + 1] = f.y;
        f = upk2(acc2[2][i]); a2f[2 * i] = f.x; a2f[2 * i + 1] = f.y;
        f = upk2(acc2[3][i]); a3[2 * i] = f.x; a3[2 * i + 1] = f.y;
    }

    const int m = m0 + row;
    const float l1 = lr[0] + lr[1] + lr[2] + lr[3];
    const int p = m & 1;
    const float l2 = p ? (lr[1] + lr[3]) : (lr[0] + lr[2]);
    const bool act2 = (p == ((m >> 10) & 1));
    const bool act3 = ((m & 3) == 0);
    const float inv1 = 1.0f / l1;
    const float inv2 = act2 ? (1.0f / l2) : 0.0f;
    const float inv3 = act3 ? (1.0f / lr[0]) : 0.0f;

    float* ob = gout + bh_off + (size_t)m * row_stride + dbase;
#pragma unroll
    for (int i = 0; i < 16; i += 4) {
        float4 o;
        float s0, s1, s2v, s3;
        s0 = a0[i + 0] + a1[i + 0] + a2f[i + 0] + a3[i + 0];
        s1 = a0[i + 1] + a1[i + 1] + a2f[i + 1] + a3[i + 1];
        s2v = a0[i + 2] + a1[i + 2] + a2f[i + 2] + a3[i + 2];
        s3 = a0[i + 3] + a1[i + 3] + a2f[i + 3] + a3[i + 3];
        float p0 = p ? (a1[i + 0] + a3[i + 0]) : (a0[i + 0] + a2f[i + 0]);
        float p1 = p ? (a1[i + 1] + a3[i + 1]) : (a0[i + 1] + a2f[i + 1]);
        float p2 = p ? (a1[i + 2] + a3[i + 2]) : (a0[i + 2] + a2f[i + 2]);
        float p3 = p ? (a1[i + 3] + a3[i + 3]) : (a0[i + 3] + a2f[i + 3]);
        o.x = s0 * inv1 + p0 * inv2 + a0[i + 0] * inv3;
        o.y = s1 * inv1 + p1 * inv2 + a0[i + 1] * inv3;
        o.z = s2v * inv1 + p2 * inv2 + a0[i + 2] * inv3;
        o.w = s3 * inv1 + p3 * inv2 + a0[i + 3] * inv3;
        *(float4*)(ob + i) = o;
    }
}

// ---- launch --------------------------------------------------------------

extern "C" void kernel_launch(void* const* d_in, const int* in_sizes, int n_in,
                              void* d_out, int out_size) {
    const float* q = (const float*)d_in[0];
    const float* k = (const float*)d_in[1];
    const float* v = (const float*)d_in[2];
    float* out = (float*)d_out;

    const size_t smem_bytes =
        (size_t)(MT * 64 + NT * KS_STRIDE + MT * ES_STRIDE + NT * 64) * sizeof(float);

    cudaFuncSetAttribute(dilated_attn_kernel,
                         cudaFuncAttributeMaxDynamicSharedMemorySize,
                         (int)smem_bytes);

    dim3 grid(SS / MT, HH, BB);
    dilated_attn_kernel<<<grid, THREADS, smem_bytes>>>(q, k, v, out);
}